// round 11
// baseline (speedup 1.0000x reference)
#include <cuda_runtime.h>
#include <cuda_fp16.h>
#include <cstdint>

// ============================================================================
// Problem constants
// ============================================================================
namespace {
constexpr int CI = 64, CO = 64, CJ = 16, B_ = 512;
constexpr int HC   = 16;          // i-chunks of 4
constexpr int KT   = 2;           // k-tiles of 16 (K = 32; bias via epilogue)
constexpr int USTRIDE = 68;       // floats per b-row in Us/Fs (64 + 4 pad)
constexpr int SMEM_HALF = 128 * USTRIDE;            // 8704 floats
constexpr int A_STEP_U4 = KT * 4 * 32;              // 256 uint4 per step
constexpr int A_STEP_FL = A_STEP_U4 * 4;            // 1024 floats
constexpr int SMEM_FLOATS = 2 * SMEM_HALF + 2 * A_STEP_FL;   // 19456
constexpr int SMEM_DYN  = SMEM_FLOATS * 4;                   // 77824 bytes
using ull = unsigned long long;
}

// A fragments (fp16): [term][j][hc][kt(2)][mt(4)][lane(32)] x uint4  -> 8.4MB
__device__ uint32_t g_wa[2 * 64 * HC * KT * 4 * 32 * 4];
// B fragments (fp16): [bt(4)][nt(16)][kt(2)][lane(32)] x uint2
__device__ uint32_t g_vb[4 * 16 * KT * 32 * 2];

// ============================================================================
// helpers
// ============================================================================
__device__ __forceinline__ uint32_t pack_h2(float lo, float hi) {
    __half2 h = __floats2half2_rn(lo, hi);
    return *(uint32_t*)&h;
}
__device__ __forceinline__ ull fma2(ull a, ull b, ull c) {
    ull d;
    asm("fma.rn.f32x2 %0, %1, %2, %3;" : "=l"(d) : "l"(a), "l"(b), "l"(c));
    return d;
}
__device__ __forceinline__ ull splat2(float x) {
    ull r;
    asm("mov.b64 %0, {%1, %1};" : "=l"(r) : "f"(x));
    return r;
}
__device__ __forceinline__ ull pack2(float lo, float hi) {
    ull r;
    asm("mov.b64 %0, {%1, %2};" : "=l"(r) : "f"(lo), "f"(hi));
    return r;
}
__device__ __forceinline__ void unpack2(ull v, float& lo, float& hi) {
    asm("mov.b64 {%0, %1}, %2;" : "=f"(lo), "=f"(hi) : "l"(v));
}
__device__ __forceinline__ void mma_f16(float c[4], uint32_t a0, uint32_t a1,
                                        uint32_t a2, uint32_t a3,
                                        uint32_t b0, uint32_t b1) {
    asm volatile(
        "mma.sync.aligned.m16n8k16.row.col.f32.f16.f16.f32 "
        "{%0,%1,%2,%3}, {%4,%5,%6,%7}, {%8,%9}, {%0,%1,%2,%3};"
        : "+f"(c[0]), "+f"(c[1]), "+f"(c[2]), "+f"(c[3])
        : "r"(a0), "r"(a1), "r"(a2), "r"(a3), "r"(b0), "r"(b1));
}
__device__ __forceinline__ void cpa16(uint32_t s, const void* g) {
    asm volatile("cp.async.cg.shared.global [%0], [%1], 16;" :: "r"(s), "l"(g));
}
__device__ __forceinline__ void cp_commit() { asm volatile("cp.async.commit_group;"); }
template <int N>
__device__ __forceinline__ void cp_wait() { asm volatile("cp.async.wait_group %0;" :: "n"(N)); }

// ============================================================================
// Fused prep (validated in R10): blocks [0,2048) = A-fragments via direct
// coalesced LDG (no smem, no barrier); blocks [2048,2064) = trig B-fragments.
// ============================================================================
__global__ void __launch_bounds__(256) prep_all(
    const float* __restrict__ theta,
    const float* __restrict__ Wc,  const float* __restrict__ Ws,
    const float* __restrict__ Wbc, const float* __restrict__ Wbs)
{
    const int blk = blockIdx.x;
    const int t   = threadIdx.x;

    if (blk < 2048) {
        const int term = blk >> 10;
        const int j    = (blk >> 4) & 63;
        const int hc   = blk & 15;
        const int lane = t & 31, mt = (t >> 5) & 3, kt = t >> 7;
        const int g = lane >> 2, tt = lane & 3;
        // kt=0 -> cos tensor, kt=1 -> sin tensor (c-offsets {0,1,8,9} of 2tt)
        const float* T = (kt == 0) ? (term ? Wbc : Wc) : (term ? Wbs : Ws);
        const float* base = T + (size_t)((j * 64 + hc * 4 + mt) * 16 + 2 * tt) * 16;
        uint4 o;
        o.x = pack_h2(base[0 * 16 + g],     base[1 * 16 + g]);
        o.y = pack_h2(base[0 * 16 + g + 8], base[1 * 16 + g + 8]);
        o.z = pack_h2(base[8 * 16 + g],     base[9 * 16 + g]);
        o.w = pack_h2(base[8 * 16 + g + 8], base[9 * 16 + g + 8]);
        ((uint4*)g_wa)[((blk * KT + kt) * 4 + mt) * 32 + lane] = o;
    } else {
        const int v = (blk - 2048) * 256 + t;
        const int lane = v & 31;
        const int kt   = (v >> 5) & 1;
        const int nt   = (v >> 6) & 15;
        const int bt   = v >> 10;
        const int g    = lane >> 2, tt = lane & 3;
        const int b    = bt * 128 + nt * 8 + g;
        const int k0   = kt * 16 + 2 * tt;
        auto vval = [&](int k) -> float {
            return (k < 16) ? cosf(theta[b * CJ + k]) : sinf(theta[b * CJ + (k - 16)]);
        };
        uint2 o;
        o.x = pack_h2(vval(k0),     vval(k0 + 1));
        o.y = pack_h2(vval(k0 + 8), vval(k0 + 9));
        ((uint2*)g_vb)[((bt * 16 + nt) * KT + kt) * 32 + lane] = o;
    }
}

// ============================================================================
// Main kernel — R9 configuration verbatim (68.3us measured):
// grid (4,64), 256 thr, occ 2, fp16 mma, single Us/Fs, 2 barriers/step
// ============================================================================
__global__ void __launch_bounds__(256, 2) main_kernel(
    const float* __restrict__ F,     // (B, CI, 4, 4)
    const float* __restrict__ Wb,    // bias term1 (flat rr = q*4+r)
    const float* __restrict__ Wbb,   // bias term2 (flat rr = p*4+q)
    float* __restrict__ out)         // (B, CO, 4, 4)
{
    extern __shared__ float sm[];
    float* Us = sm;
    float* Fs = sm + SMEM_HALF;
    float* A0 = sm + 2 * SMEM_HALF;
    float* A1 = A0 + A_STEP_FL;

    const int tid  = threadIdx.x;
    const int wid  = tid >> 5;
    const int lane = tid & 31;
    const int bt   = blockIdx.x;
    const int j    = blockIdx.y;
    const int wm   = wid & 1;
    const int wn   = wid >> 1;
    const int gid  = lane >> 2;
    const int tig  = lane & 3;
    const int b_l  = tid >> 1;       // paired lanes share b (LDS broadcast)
    const int p0   = (tid & 1) * 2;

    ull o01[2] = {0ull, 0ull}, o23[2] = {0ull, 0ull};

    uint2 vb[KT][4];
    {
        const uint2* Vb = (const uint2*)g_vb;
#pragma unroll
        for (int kt = 0; kt < KT; kt++)
#pragma unroll
            for (int fn = 0; fn < 4; fn++)
                vb[kt][fn] = Vb[((bt * 16 + wn * 4 + fn) * KT + kt) * 32 + lane];
    }

    auto prefetch_A = [&](int s, float* dst) {
        const int term = s & 1, hc = s >> 1;
        const uint4* src = ((const uint4*)g_wa) +
                           (size_t)((term * 1024 + j * 16 + hc) * KT) * 128;
        const uint32_t sa = (uint32_t)__cvta_generic_to_shared(dst);
        cpa16(sa + (uint32_t)tid * 16u, src + tid);
    };

    auto stage_F = [&](int hc) {
        const uint32_t sa = (uint32_t)__cvta_generic_to_shared(Fs);
#pragma unroll
        for (int pass = 0; pass < 8; pass++) {
            const int v  = pass * 256 + tid;
            const int bb = v >> 4;
            const int x  = v & 15;
            cpa16(sa + (uint32_t)(bb * USTRIDE + x * 4) * 4u,
                  ((const float4*)F) + (size_t)(bt * 128 + bb) * 256 +
                  (hc * 4 + (x >> 2)) * 4 + (x & 3));
        }
        cp_commit();
    };

    auto apply_prev = [&](int pterm) {
        const float* ub = Us + b_l * USTRIDE;
        const float* fb = Fs + b_l * USTRIDE;
        if (pterm == 0) {
#pragma unroll
            for (int il = 0; il < 4; il++) {
                ulonglong2 uq[4];
#pragma unroll
                for (int q = 0; q < 4; q++)
                    uq[q] = *(const ulonglong2*)(ub + il * 16 + q * 4);
#pragma unroll
                for (int pp = 0; pp < 2; pp++) {
                    const float4 f = *(const float4*)(fb + il * 16 + (p0 + pp) * 4);
                    const float fv[4] = {f.x, f.y, f.z, f.w};
#pragma unroll
                    for (int q = 0; q < 4; q++) {
                        const ull fs = splat2(fv[q]);
                        o01[pp] = fma2(fs, uq[q].x, o01[pp]);
                        o23[pp] = fma2(fs, uq[q].y, o23[pp]);
                    }
                }
            }
        } else {
#pragma unroll
            for (int il = 0; il < 4; il++) {
                ull f01[4], f23[4];
#pragma unroll
                for (int q = 0; q < 4; q++) {
                    const float4 fq = *(const float4*)(fb + il * 16 + q * 4);
                    f01[q] = pack2(fq.x, fq.y);
                    f23[q] = pack2(fq.z, fq.w);
                }
#pragma unroll
                for (int pp = 0; pp < 2; pp++) {
                    const float4 u = *(const float4*)(ub + il * 16 + (p0 + pp) * 4);
                    const float uv[4] = {u.x, u.y, u.z, u.w};
#pragma unroll
                    for (int q = 0; q < 4; q++) {
                        const ull gs = splat2(uv[q]);
                        o01[pp] = fma2(gs, f01[q], o01[pp]);
                        o23[pp] = fma2(gs, f23[q], o23[pp]);
                    }
                }
            }
        }
    };

    prefetch_A(0, A0);
    cp_commit();

    for (int s = 0; s < 2 * HC; s++) {
        const int term = s & 1;
        const int hc   = s >> 1;

        if (s + 1 < 2 * HC) {
            prefetch_A(s + 1, (s & 1) ? A0 : A1);
            cp_commit();
            cp_wait<1>();
        } else {
            cp_wait<0>();
        }
        __syncthreads();

        float c[2][4][4];
#pragma unroll
        for (int fm = 0; fm < 2; fm++)
#pragma unroll
            for (int fn = 0; fn < 4; fn++)
#pragma unroll
                for (int e = 0; e < 4; e++) c[fm][fn][e] = 0.0f;

        const uint4* As = (const uint4*)((s & 1) ? A1 : A0);
#pragma unroll
        for (int kt = 0; kt < KT; kt++) {
            uint4 a[2];
            a[0] = As[(kt * 4 + wm * 2 + 0) * 32 + lane];
            a[1] = As[(kt * 4 + wm * 2 + 1) * 32 + lane];
#pragma unroll
            for (int fm = 0; fm < 2; fm++)
#pragma unroll
                for (int fn = 0; fn < 4; fn++)
                    mma_f16(c[fm][fn], a[fm].x, a[fm].y, a[fm].z, a[fm].w,
                            vb[kt][fn].x, vb[kt][fn].y);
        }

        if (s > 0) apply_prev(1 - term);

        {
            const float* bias = term ? Wbb : Wb;
#pragma unroll
            for (int fm = 0; fm < 2; fm++) {
                const int i_g = hc * 4 + wm * 2 + fm;
                const float blo = bias[(size_t)(j * 64 + i_g) * 16 + gid];
                const float bhi = bias[(size_t)(j * 64 + i_g) * 16 + gid + 8];
#pragma unroll
                for (int fn = 0; fn < 4; fn++) {
                    c[fm][fn][0] += blo;
                    c[fm][fn][1] += blo;
                    c[fm][fn][2] += bhi;
                    c[fm][fn][3] += bhi;
                }
            }
        }

        __syncthreads();

#pragma unroll
        for (int fm = 0; fm < 2; fm++)
#pragma unroll
            for (int fn = 0; fn < 4; fn++) {
                const int m = (wm * 2 + fm) * 16 + gid;
                const int n = (wn * 4 + fn) * 8 + 2 * tig;
                Us[n * USTRIDE + m]           = c[fm][fn][0];
                Us[(n + 1) * USTRIDE + m]     = c[fm][fn][1];
                Us[n * USTRIDE + m + 8]       = c[fm][fn][2];
                Us[(n + 1) * USTRIDE + m + 8] = c[fm][fn][3];
            }

        if (term == 0) stage_F(hc);
    }

    cp_wait<0>();
    __syncthreads();
    apply_prev(1);

#pragma unroll
    for (int pp = 0; pp < 2; pp++) {
        float4 o;
        unpack2(o01[pp], o.x, o.y);
        unpack2(o23[pp], o.z, o.w);
        ((float4*)out)[(size_t)((bt * 128 + b_l) * 64 + j) * 4 + (p0 + pp)] = o;
    }
}

// ============================================================================
// Launch
// ============================================================================
extern "C" void kernel_launch(void* const* d_in, const int* in_sizes, int n_in,
                              void* d_out, int out_size) {
    (void)in_sizes; (void)n_in; (void)out_size;
    const float* F   = (const float*)d_in[0];
    const float* th  = (const float*)d_in[1];
    const float* Wb  = (const float*)d_in[2];
    const float* Wc  = (const float*)d_in[3];
    const float* Ws  = (const float*)d_in[4];
    const float* Wbb = (const float*)d_in[5];
    const float* Wbc = (const float*)d_in[6];
    const float* Wbs = (const float*)d_in[7];

    cudaFuncSetAttribute(main_kernel, cudaFuncAttributeMaxDynamicSharedMemorySize, SMEM_DYN);

    prep_all<<<2064, 256>>>(th, Wc, Ws, Wbc, Wbs);
    main_kernel<<<dim3(4, 64), 256, SMEM_DYN>>>(F, Wb, Wbb, (float*)d_out);
}

// round 12
// speedup vs baseline: 1.4508x; 1.4508x over previous
#include <cuda_runtime.h>
#include <cuda_fp16.h>
#include <cstdint>

// ============================================================================
// Problem constants
// ============================================================================
namespace {
constexpr int CI = 64, CO = 64, CJ = 16, B_ = 512;
constexpr int HC   = 16;          // i-chunks of 4
constexpr int KT   = 2;           // k-tiles of 16 (K = 32; bias via epilogue)
constexpr int USTRIDE = 68;       // floats per b-row in Us/Fs (64 + 4 pad)
constexpr int SMEM_HALF = 128 * USTRIDE;            // 8704 floats
constexpr int A_STEP_U4 = KT * 4 * 32;              // 256 uint4 per step
constexpr int A_STEP_FL = A_STEP_U4 * 4;            // 1024 floats
constexpr int SMEM_FLOATS = 2 * SMEM_HALF + 2 * A_STEP_FL;   // 19456
constexpr int SMEM_DYN  = SMEM_FLOATS * 4;                   // 77824 bytes
using ull = unsigned long long;
}

// A fragments (fp16): [term][j][hc][kt(2)][mt(4)][lane(32)] x uint4  -> 8.4MB
__device__ uint32_t g_wa[2 * 64 * HC * KT * 4 * 32 * 4];
// B fragments (fp16): [bt(4)][nt(16)][kt(2)][lane(32)] x uint2
__device__ uint32_t g_vb[4 * 16 * KT * 32 * 2];

// ============================================================================
// helpers
// ============================================================================
__device__ __forceinline__ uint32_t pack_h2(float lo, float hi) {
    __half2 h = __floats2half2_rn(lo, hi);
    return *(uint32_t*)&h;
}
__device__ __forceinline__ ull fma2(ull a, ull b, ull c) {
    ull d;
    asm("fma.rn.f32x2 %0, %1, %2, %3;" : "=l"(d) : "l"(a), "l"(b), "l"(c));
    return d;
}
__device__ __forceinline__ ull splat2(float x) {
    ull r;
    asm("mov.b64 %0, {%1, %1};" : "=l"(r) : "f"(x));
    return r;
}
__device__ __forceinline__ ull pack2(float lo, float hi) {
    ull r;
    asm("mov.b64 %0, {%1, %2};" : "=l"(r) : "f"(lo), "f"(hi));
    return r;
}
__device__ __forceinline__ void unpack2(ull v, float& lo, float& hi) {
    asm("mov.b64 {%0, %1}, %2;" : "=f"(lo), "=f"(hi) : "l"(v));
}
__device__ __forceinline__ void mma_f16(float c[4], uint32_t a0, uint32_t a1,
                                        uint32_t a2, uint32_t a3,
                                        uint32_t b0, uint32_t b1) {
    asm volatile(
        "mma.sync.aligned.m16n8k16.row.col.f32.f16.f16.f32 "
        "{%0,%1,%2,%3}, {%4,%5,%6,%7}, {%8,%9}, {%0,%1,%2,%3};"
        : "+f"(c[0]), "+f"(c[1]), "+f"(c[2]), "+f"(c[3])
        : "r"(a0), "r"(a1), "r"(a2), "r"(a3), "r"(b0), "r"(b1));
}
__device__ __forceinline__ void cpa16(uint32_t s, const void* g) {
    asm volatile("cp.async.cg.shared.global [%0], [%1], 16;" :: "r"(s), "l"(g));
}
__device__ __forceinline__ void cp_commit() { asm volatile("cp.async.commit_group;"); }
template <int N>
__device__ __forceinline__ void cp_wait() { asm volatile("cp.async.wait_group %0;" :: "n"(N)); }

// ============================================================================
// Prep 1: weight A-fragments (fp16, m16n8k16 layout)
//   K=32: k 0..15 = cos(c=k), 16..31 = sin(c=k-16)
//   frag: x=(g,2t|2t+1), y=(g+8,..), z=(g,2t+8|2t+9), w=(g+8,..)
// ============================================================================
__global__ void __launch_bounds__(256) prep_w(
    const float* __restrict__ Wc,  const float* __restrict__ Ws,
    const float* __restrict__ Wbc, const float* __restrict__ Wbs)
{
    __shared__ float sC[4][256], sS[4][256];
    const int bid  = blockIdx.x;
    const int term = bid >> 10;
    const int j    = (bid >> 4) & 63;
    const int hc   = bid & 15;
    const int i0   = hc * 4;
    const int t    = threadIdx.x;

    const float* pC = term ? Wbc : Wc;
    const float* pS = term ? Wbs : Ws;

    ((float4*)sC)[t] = ((const float4*)(pC + (size_t)(j * 64 + i0) * 256))[t];
    ((float4*)sS)[t] = ((const float4*)(pS + (size_t)(j * 64 + i0) * 256))[t];
    __syncthreads();

    auto wval = [&](int i, int rr, int k) -> float {
        return (k < 16) ? sC[i][k * 16 + rr] : sS[i][(k - 16) * 16 + rr];
    };

    // 256 fragments (kt*mt*lane), one per thread
    {
        const int lane = t & 31, mt = (t >> 5) & 3, kt = t >> 7;
        const int g = lane >> 2, tt = lane & 3;
        const int k0 = kt * 16 + 2 * tt;
        uint4 o;
        o.x = pack_h2(wval(mt, g,     k0),     wval(mt, g,     k0 + 1));
        o.y = pack_h2(wval(mt, g + 8, k0),     wval(mt, g + 8, k0 + 1));
        o.z = pack_h2(wval(mt, g,     k0 + 8), wval(mt, g,     k0 + 9));
        o.w = pack_h2(wval(mt, g + 8, k0 + 8), wval(mt, g + 8, k0 + 9));
        ((uint4*)g_wa)[((bid * KT + kt) * 4 + mt) * 32 + lane] = o;
    }
}

// ============================================================================
// Prep 2: trig B-fragments (fp16, m16n8k16 col-major B)
//   b0 = v[k0..k0+1][n], b1 = v[k0+8..k0+9][n]
// ============================================================================
__global__ void __launch_bounds__(256) prep_v(const float* __restrict__ theta) {
    const int t = blockIdx.x * 256 + threadIdx.x;   // 4096 total
    const int lane = t & 31;
    const int kt   = (t >> 5) & 1;
    const int nt   = (t >> 6) & 15;
    const int bt   = t >> 10;
    const int g    = lane >> 2, tt = lane & 3;
    const int b    = bt * 128 + nt * 8 + g;
    const int k0   = kt * 16 + 2 * tt;

    auto vval = [&](int k) -> float {
        return (k < 16) ? cosf(theta[b * CJ + k]) : sinf(theta[b * CJ + (k - 16)]);
    };
    uint2 o;
    o.x = pack_h2(vval(k0),     vval(k0 + 1));
    o.y = pack_h2(vval(k0 + 8), vval(k0 + 9));
    ((uint2*)g_vb)[((bt * 16 + nt) * KT + kt) * 32 + lane] = o;
}

// ============================================================================
// Main kernel — R9 config (grid 4x64, occ 2) + fp16 mma
// ============================================================================
__global__ void __launch_bounds__(256, 2) main_kernel(
    const float* __restrict__ F,     // (B, CI, 4, 4)
    const float* __restrict__ Wb,    // bias term1 (flat rr = q*4+r)
    const float* __restrict__ Wbb,   // bias term2 (flat rr = p*4+q)
    float* __restrict__ out)         // (B, CO, 4, 4)
{
    extern __shared__ float sm[];
    float* Us = sm;
    float* Fs = sm + SMEM_HALF;
    float* A0 = sm + 2 * SMEM_HALF;
    float* A1 = A0 + A_STEP_FL;

    const int tid  = threadIdx.x;
    const int wid  = tid >> 5;
    const int lane = tid & 31;
    const int bt   = blockIdx.x;
    const int j    = blockIdx.y;
    const int wm   = wid & 1;
    const int wn   = wid >> 1;
    const int gid  = lane >> 2;
    const int tig  = lane & 3;
    const int b_l  = tid >> 1;       // paired lanes share b (LDS broadcast)
    const int p0   = (tid & 1) * 2;

    ull o01[2] = {0ull, 0ull}, o23[2] = {0ull, 0ull};

    // Vb fragments in registers (fp16; 16 regs)
    uint2 vb[KT][4];
    {
        const uint2* Vb = (const uint2*)g_vb;
#pragma unroll
        for (int kt = 0; kt < KT; kt++)
#pragma unroll
            for (int fn = 0; fn < 4; fn++)
                vb[kt][fn] = Vb[((bt * 16 + wn * 4 + fn) * KT + kt) * 32 + lane];
    }

    auto prefetch_A = [&](int s, float* dst) {
        const int term = s & 1, hc = s >> 1;
        const uint4* src = ((const uint4*)g_wa) +
                           (size_t)((term * 1024 + j * 16 + hc) * KT) * 128;
        const uint32_t sa = (uint32_t)__cvta_generic_to_shared(dst);
        cpa16(sa + (uint32_t)tid * 16u, src + tid);   // 256 uint4, one/thread
    };

    auto stage_F = [&](int hc) {
        const uint32_t sa = (uint32_t)__cvta_generic_to_shared(Fs);
#pragma unroll
        for (int pass = 0; pass < 8; pass++) {
            const int v  = pass * 256 + tid;
            const int bb = v >> 4;
            const int x  = v & 15;
            cpa16(sa + (uint32_t)(bb * USTRIDE + x * 4) * 4u,
                  ((const float4*)F) + (size_t)(bt * 128 + bb) * 256 +
                  (hc * 4 + (x >> 2)) * 4 + (x & 3));
        }
        cp_commit();
    };

    auto apply_prev = [&](int pterm) {
        const float* ub = Us + b_l * USTRIDE;
        const float* fb = Fs + b_l * USTRIDE;
        if (pterm == 0) {
#pragma unroll
            for (int il = 0; il < 4; il++) {
                ulonglong2 uq[4];
#pragma unroll
                for (int q = 0; q < 4; q++)
                    uq[q] = *(const ulonglong2*)(ub + il * 16 + q * 4);
#pragma unroll
                for (int pp = 0; pp < 2; pp++) {
                    const float4 f = *(const float4*)(fb + il * 16 + (p0 + pp) * 4);
                    const float fv[4] = {f.x, f.y, f.z, f.w};
#pragma unroll
                    for (int q = 0; q < 4; q++) {
                        const ull fs = splat2(fv[q]);
                        o01[pp] = fma2(fs, uq[q].x, o01[pp]);
                        o23[pp] = fma2(fs, uq[q].y, o23[pp]);
                    }
                }
            }
        } else {
#pragma unroll
            for (int il = 0; il < 4; il++) {
                ull f01[4], f23[4];
#pragma unroll
                for (int q = 0; q < 4; q++) {
                    const float4 fq = *(const float4*)(fb + il * 16 + q * 4);
                    f01[q] = pack2(fq.x, fq.y);
                    f23[q] = pack2(fq.z, fq.w);
                }
#pragma unroll
                for (int pp = 0; pp < 2; pp++) {
                    const float4 u = *(const float4*)(ub + il * 16 + (p0 + pp) * 4);
                    const float uv[4] = {u.x, u.y, u.z, u.w};
#pragma unroll
                    for (int q = 0; q < 4; q++) {
                        const ull gs = splat2(uv[q]);
                        o01[pp] = fma2(gs, f01[q], o01[pp]);
                        o23[pp] = fma2(gs, f23[q], o23[pp]);
                    }
                }
            }
        }
    };

    prefetch_A(0, A0);
    cp_commit();

    for (int s = 0; s < 2 * HC; s++) {
        const int term = s & 1;
        const int hc   = s >> 1;

        if (s + 1 < 2 * HC) {
            prefetch_A(s + 1, (s & 1) ? A0 : A1);
            cp_commit();
            cp_wait<1>();
        } else {
            cp_wait<0>();
        }
        __syncthreads();

        // ==== interleave: mma(s) + apply(s-1) on disjoint pipes ====
        float c[2][4][4];
#pragma unroll
        for (int fm = 0; fm < 2; fm++)
#pragma unroll
            for (int fn = 0; fn < 4; fn++)
#pragma unroll
                for (int e = 0; e < 4; e++) c[fm][fn][e] = 0.0f;

        const uint4* As = (const uint4*)((s & 1) ? A1 : A0);
#pragma unroll
        for (int kt = 0; kt < KT; kt++) {
            uint4 a[2];
            a[0] = As[(kt * 4 + wm * 2 + 0) * 32 + lane];
            a[1] = As[(kt * 4 + wm * 2 + 1) * 32 + lane];
#pragma unroll
            for (int fm = 0; fm < 2; fm++)
#pragma unroll
                for (int fn = 0; fn < 4; fn++)
                    mma_f16(c[fm][fn], a[fm].x, a[fm].y, a[fm].z, a[fm].w,
                            vb[kt][fn].x, vb[kt][fn].y);
        }

        if (s > 0) apply_prev(1 - term);

        // bias add in fp32
        {
            const float* bias = term ? Wbb : Wb;
#pragma unroll
            for (int fm = 0; fm < 2; fm++) {
                const int i_g = hc * 4 + wm * 2 + fm;
                const float blo = bias[(size_t)(j * 64 + i_g) * 16 + gid];
                const float bhi = bias[(size_t)(j * 64 + i_g) * 16 + gid + 8];
#pragma unroll
                for (int fn = 0; fn < 4; fn++) {
                    c[fm][fn][0] += blo;
                    c[fm][fn][1] += blo;
                    c[fm][fn][2] += bhi;
                    c[fm][fn][3] += bhi;
                }
            }
        }

        __syncthreads();

        // ==== post: store Us(s); stage Fs(hc) on term0 steps ====
#pragma unroll
        for (int fm = 0; fm < 2; fm++)
#pragma unroll
            for (int fn = 0; fn < 4; fn++) {
                const int m = (wm * 2 + fm) * 16 + gid;
                const int n = (wn * 4 + fn) * 8 + 2 * tig;
                Us[n * USTRIDE + m]           = c[fm][fn][0];
                Us[(n + 1) * USTRIDE + m]     = c[fm][fn][1];
                Us[n * USTRIDE + m + 8]       = c[fm][fn][2];
                Us[(n + 1) * USTRIDE + m + 8] = c[fm][fn][3];
            }

        if (term == 0) stage_F(hc);
    }

    // ==== tail ====
    cp_wait<0>();
    __syncthreads();
    apply_prev(1);

#pragma unroll
    for (int pp = 0; pp < 2; pp++) {
        float4 o;
        unpack2(o01[pp], o.x, o.y);
        unpack2(o23[pp], o.z, o.w);
        ((float4*)out)[(size_t)((bt * 128 + b_l) * 64 + j) * 4 + (p0 + pp)] = o;
    }
}

// ============================================================================
// Launch
// ============================================================================
extern "C" void kernel_launch(void* const* d_in, const int* in_sizes, int n_in,
                              void* d_out, int out_size) {
    (void)in_sizes; (void)n_in; (void)out_size;
    const float* F   = (const float*)d_in[0];
    const float* th  = (const float*)d_in[1];
    const float* Wb  = (const float*)d_in[2];
    const float* Wc  = (const float*)d_in[3];
    const float* Ws  = (const float*)d_in[4];
    const float* Wbb = (const float*)d_in[5];
    const float* Wbc = (const float*)d_in[6];
    const float* Wbs = (const float*)d_in[7];

    cudaFuncSetAttribute(main_kernel, cudaFuncAttributeMaxDynamicSharedMemorySize, SMEM_DYN);

    prep_w<<<2 * 64 * HC, 256>>>(Wc, Ws, Wbc, Wbs);
    prep_v<<<16, 256>>>(th);
    main_kernel<<<dim3(4, 64), 256, SMEM_DYN>>>(F, Wb, Wbb, (float*)d_out);
}

// round 13
// speedup vs baseline: 1.4978x; 1.0324x over previous
#include <cuda_runtime.h>
#include <cuda_fp16.h>
#include <cstdint>

// ============================================================================
// Problem constants
// ============================================================================
namespace {
constexpr int CI = 64, CO = 64, CJ = 16, B_ = 512;
constexpr int HC   = 16;          // i-chunks of 4
constexpr int KT   = 2;           // k-tiles of 16 (K = 32; bias via epilogue)
constexpr int USTRIDE = 68;       // floats per b-row in Us/Fs (64 + 4 pad)
constexpr int SMEM_HALF = 128 * USTRIDE;            // 8704 floats
constexpr int A_STEP_U4 = KT * 4 * 32;              // 256 uint4 per step
constexpr int A_STEP_FL = A_STEP_U4 * 4;            // 1024 floats
constexpr int SMEM_FLOATS = 2 * SMEM_HALF + 2 * A_STEP_FL;   // 19456
constexpr int SMEM_DYN  = SMEM_FLOATS * 4;                   // 77824 bytes
using ull = unsigned long long;
}

// A fragments (fp16): [term][j][hc][kt(2)][mt(4)][lane(32)] x uint4  -> 8.4MB
__device__ uint32_t g_wa[2 * 64 * HC * KT * 4 * 32 * 4];
// B fragments (fp16): [bt(4)][nt(16)][kt(2)][lane(32)] x uint2
__device__ uint32_t g_vb[4 * 16 * KT * 32 * 2];

// ============================================================================
// helpers
// ============================================================================
__device__ __forceinline__ uint32_t pack_h2(float lo, float hi) {
    __half2 h = __floats2half2_rn(lo, hi);
    return *(uint32_t*)&h;
}
__device__ __forceinline__ ull fma2(ull a, ull b, ull c) {
    ull d;
    asm("fma.rn.f32x2 %0, %1, %2, %3;" : "=l"(d) : "l"(a), "l"(b), "l"(c));
    return d;
}
__device__ __forceinline__ ull splat2(float x) {
    ull r;
    asm("mov.b64 %0, {%1, %1};" : "=l"(r) : "f"(x));
    return r;
}
__device__ __forceinline__ ull pack2(float lo, float hi) {
    ull r;
    asm("mov.b64 %0, {%1, %2};" : "=l"(r) : "f"(lo), "f"(hi));
    return r;
}
__device__ __forceinline__ void unpack2(ull v, float& lo, float& hi) {
    asm("mov.b64 {%0, %1}, %2;" : "=f"(lo), "=f"(hi) : "l"(v));
}
__device__ __forceinline__ void mma_f16(float c[4], uint32_t a0, uint32_t a1,
                                        uint32_t a2, uint32_t a3,
                                        uint32_t b0, uint32_t b1) {
    asm volatile(
        "mma.sync.aligned.m16n8k16.row.col.f32.f16.f16.f32 "
        "{%0,%1,%2,%3}, {%4,%5,%6,%7}, {%8,%9}, {%0,%1,%2,%3};"
        : "+f"(c[0]), "+f"(c[1]), "+f"(c[2]), "+f"(c[3])
        : "r"(a0), "r"(a1), "r"(a2), "r"(a3), "r"(b0), "r"(b1));
}
__device__ __forceinline__ void cpa16(uint32_t s, const void* g) {
    asm volatile("cp.async.cg.shared.global [%0], [%1], 16;" :: "r"(s), "l"(g));
}
__device__ __forceinline__ void cp_commit() { asm volatile("cp.async.commit_group;"); }
template <int N>
__device__ __forceinline__ void cp_wait() { asm volatile("cp.async.wait_group %0;" :: "n"(N)); }

// ============================================================================
// Fused prep (validated R10+R11, ~1.6us): blocks [0,2048) = A-fragments via
// direct sector-coalesced LDG (no smem, no barrier); [2048,2064) = trig B.
// ============================================================================
__global__ void __launch_bounds__(256) prep_all(
    const float* __restrict__ theta,
    const float* __restrict__ Wc,  const float* __restrict__ Ws,
    const float* __restrict__ Wbc, const float* __restrict__ Wbs)
{
    const int blk = blockIdx.x;
    const int t   = threadIdx.x;

    if (blk < 2048) {
        const int term = blk >> 10;
        const int j    = (blk >> 4) & 63;
        const int hc   = blk & 15;
        const int lane = t & 31, mt = (t >> 5) & 3, kt = t >> 7;
        const int g = lane >> 2, tt = lane & 3;
        // kt=0 -> cos tensor, kt=1 -> sin tensor (c-offsets {0,1,8,9} of 2tt)
        const float* T = (kt == 0) ? (term ? Wbc : Wc) : (term ? Wbs : Ws);
        const float* base = T + (size_t)((j * 64 + hc * 4 + mt) * 16 + 2 * tt) * 16;
        uint4 o;
        o.x = pack_h2(base[0 * 16 + g],     base[1 * 16 + g]);
        o.y = pack_h2(base[0 * 16 + g + 8], base[1 * 16 + g + 8]);
        o.z = pack_h2(base[8 * 16 + g],     base[9 * 16 + g]);
        o.w = pack_h2(base[8 * 16 + g + 8], base[9 * 16 + g + 8]);
        ((uint4*)g_wa)[((blk * KT + kt) * 4 + mt) * 32 + lane] = o;
    } else {
        const int v = (blk - 2048) * 256 + t;
        const int lane = v & 31;
        const int kt   = (v >> 5) & 1;
        const int nt   = (v >> 6) & 15;
        const int bt   = v >> 10;
        const int g    = lane >> 2, tt = lane & 3;
        const int b    = bt * 128 + nt * 8 + g;
        const int k0   = kt * 16 + 2 * tt;
        auto vval = [&](int k) -> float {
            return (k < 16) ? cosf(theta[b * CJ + k]) : sinf(theta[b * CJ + (k - 16)]);
        };
        uint2 o;
        o.x = pack_h2(vval(k0),     vval(k0 + 1));
        o.y = pack_h2(vval(k0 + 8), vval(k0 + 9));
        ((uint2*)g_vb)[((bt * 16 + nt) * KT + kt) * 32 + lane] = o;
    }
}

// ============================================================================
// Main kernel — byte-identical to R12 (reproduced 68.3us):
// grid (4,64), 256 thr, occ 2, fp16 mma, single Us/Fs, 2 barriers/step
// ============================================================================
__global__ void __launch_bounds__(256, 2) main_kernel(
    const float* __restrict__ F,     // (B, CI, 4, 4)
    const float* __restrict__ Wb,    // bias term1 (flat rr = q*4+r)
    const float* __restrict__ Wbb,   // bias term2 (flat rr = p*4+q)
    float* __restrict__ out)         // (B, CO, 4, 4)
{
    extern __shared__ float sm[];
    float* Us = sm;
    float* Fs = sm + SMEM_HALF;
    float* A0 = sm + 2 * SMEM_HALF;
    float* A1 = A0 + A_STEP_FL;

    const int tid  = threadIdx.x;
    const int wid  = tid >> 5;
    const int lane = tid & 31;
    const int bt   = blockIdx.x;
    const int j    = blockIdx.y;
    const int wm   = wid & 1;
    const int wn   = wid >> 1;
    const int gid  = lane >> 2;
    const int tig  = lane & 3;
    const int b_l  = tid >> 1;       // paired lanes share b (LDS broadcast)
    const int p0   = (tid & 1) * 2;

    ull o01[2] = {0ull, 0ull}, o23[2] = {0ull, 0ull};

    uint2 vb[KT][4];
    {
        const uint2* Vb = (const uint2*)g_vb;
#pragma unroll
        for (int kt = 0; kt < KT; kt++)
#pragma unroll
            for (int fn = 0; fn < 4; fn++)
                vb[kt][fn] = Vb[((bt * 16 + wn * 4 + fn) * KT + kt) * 32 + lane];
    }

    auto prefetch_A = [&](int s, float* dst) {
        const int term = s & 1, hc = s >> 1;
        const uint4* src = ((const uint4*)g_wa) +
                           (size_t)((term * 1024 + j * 16 + hc) * KT) * 128;
        const uint32_t sa = (uint32_t)__cvta_generic_to_shared(dst);
        cpa16(sa + (uint32_t)tid * 16u, src + tid);
    };

    auto stage_F = [&](int hc) {
        const uint32_t sa = (uint32_t)__cvta_generic_to_shared(Fs);
#pragma unroll
        for (int pass = 0; pass < 8; pass++) {
            const int v  = pass * 256 + tid;
            const int bb = v >> 4;
            const int x  = v & 15;
            cpa16(sa + (uint32_t)(bb * USTRIDE + x * 4) * 4u,
                  ((const float4*)F) + (size_t)(bt * 128 + bb) * 256 +
                  (hc * 4 + (x >> 2)) * 4 + (x & 3));
        }
        cp_commit();
    };

    auto apply_prev = [&](int pterm) {
        const float* ub = Us + b_l * USTRIDE;
        const float* fb = Fs + b_l * USTRIDE;
        if (pterm == 0) {
#pragma unroll
            for (int il = 0; il < 4; il++) {
                ulonglong2 uq[4];
#pragma unroll
                for (int q = 0; q < 4; q++)
                    uq[q] = *(const ulonglong2*)(ub + il * 16 + q * 4);
#pragma unroll
                for (int pp = 0; pp < 2; pp++) {
                    const float4 f = *(const float4*)(fb + il * 16 + (p0 + pp) * 4);
                    const float fv[4] = {f.x, f.y, f.z, f.w};
#pragma unroll
                    for (int q = 0; q < 4; q++) {
                        const ull fs = splat2(fv[q]);
                        o01[pp] = fma2(fs, uq[q].x, o01[pp]);
                        o23[pp] = fma2(fs, uq[q].y, o23[pp]);
                    }
                }
            }
        } else {
#pragma unroll
            for (int il = 0; il < 4; il++) {
                ull f01[4], f23[4];
#pragma unroll
                for (int q = 0; q < 4; q++) {
                    const float4 fq = *(const float4*)(fb + il * 16 + q * 4);
                    f01[q] = pack2(fq.x, fq.y);
                    f23[q] = pack2(fq.z, fq.w);
                }
#pragma unroll
                for (int pp = 0; pp < 2; pp++) {
                    const float4 u = *(const float4*)(ub + il * 16 + (p0 + pp) * 4);
                    const float uv[4] = {u.x, u.y, u.z, u.w};
#pragma unroll
                    for (int q = 0; q < 4; q++) {
                        const ull gs = splat2(uv[q]);
                        o01[pp] = fma2(gs, f01[q], o01[pp]);
                        o23[pp] = fma2(gs, f23[q], o23[pp]);
                    }
                }
            }
        }
    };

    prefetch_A(0, A0);
    cp_commit();

    for (int s = 0; s < 2 * HC; s++) {
        const int term = s & 1;
        const int hc   = s >> 1;

        if (s + 1 < 2 * HC) {
            prefetch_A(s + 1, (s & 1) ? A0 : A1);
            cp_commit();
            cp_wait<1>();
        } else {
            cp_wait<0>();
        }
        __syncthreads();

        float c[2][4][4];
#pragma unroll
        for (int fm = 0; fm < 2; fm++)
#pragma unroll
            for (int fn = 0; fn < 4; fn++)
#pragma unroll
                for (int e = 0; e < 4; e++) c[fm][fn][e] = 0.0f;

        const uint4* As = (const uint4*)((s & 1) ? A1 : A0);
#pragma unroll
        for (int kt = 0; kt < KT; kt++) {
            uint4 a[2];
            a[0] = As[(kt * 4 + wm * 2 + 0) * 32 + lane];
            a[1] = As[(kt * 4 + wm * 2 + 1) * 32 + lane];
#pragma unroll
            for (int fm = 0; fm < 2; fm++)
#pragma unroll
                for (int fn = 0; fn < 4; fn++)
                    mma_f16(c[fm][fn], a[fm].x, a[fm].y, a[fm].z, a[fm].w,
                            vb[kt][fn].x, vb[kt][fn].y);
        }

        if (s > 0) apply_prev(1 - term);

        {
            const float* bias = term ? Wbb : Wb;
#pragma unroll
            for (int fm = 0; fm < 2; fm++) {
                const int i_g = hc * 4 + wm * 2 + fm;
                const float blo = bias[(size_t)(j * 64 + i_g) * 16 + gid];
                const float bhi = bias[(size_t)(j * 64 + i_g) * 16 + gid + 8];
#pragma unroll
                for (int fn = 0; fn < 4; fn++) {
                    c[fm][fn][0] += blo;
                    c[fm][fn][1] += blo;
                    c[fm][fn][2] += bhi;
                    c[fm][fn][3] += bhi;
                }
            }
        }

        __syncthreads();

#pragma unroll
        for (int fm = 0; fm < 2; fm++)
#pragma unroll
            for (int fn = 0; fn < 4; fn++) {
                const int m = (wm * 2 + fm) * 16 + gid;
                const int n = (wn * 4 + fn) * 8 + 2 * tig;
                Us[n * USTRIDE + m]           = c[fm][fn][0];
                Us[(n + 1) * USTRIDE + m]     = c[fm][fn][1];
                Us[n * USTRIDE + m + 8]       = c[fm][fn][2];
                Us[(n + 1) * USTRIDE + m + 8] = c[fm][fn][3];
            }

        if (term == 0) stage_F(hc);
    }

    cp_wait<0>();
    __syncthreads();
    apply_prev(1);

#pragma unroll
    for (int pp = 0; pp < 2; pp++) {
        float4 o;
        unpack2(o01[pp], o.x, o.y);
        unpack2(o23[pp], o.z, o.w);
        ((float4*)out)[(size_t)((bt * 128 + b_l) * 64 + j) * 4 + (p0 + pp)] = o;
    }
}

// ============================================================================
// Launch
// ============================================================================
extern "C" void kernel_launch(void* const* d_in, const int* in_sizes, int n_in,
                              void* d_out, int out_size) {
    (void)in_sizes; (void)n_in; (void)out_size;
    const float* F   = (const float*)d_in[0];
    const float* th  = (const float*)d_in[1];
    const float* Wb  = (const float*)d_in[2];
    const float* Wc  = (const float*)d_in[3];
    const float* Ws  = (const float*)d_in[4];
    const float* Wbb = (const float*)d_in[5];
    const float* Wbc = (const float*)d_in[6];
    const float* Wbs = (const float*)d_in[7];

    cudaFuncSetAttribute(main_kernel, cudaFuncAttributeMaxDynamicSharedMemorySize, SMEM_DYN);

    prep_all<<<2064, 256>>>(th, Wc, Ws, Wbc, Wbs);
    main_kernel<<<dim3(4, 64), 256, SMEM_DYN>>>(F, Wb, Wbb, (float*)d_out);
}